// round 2
// baseline (speedup 1.0000x reference)
#include <cuda_runtime.h>
#include <math.h>

#define Bn 8
#define An 100000
#define Kn 80
#define Mn 32
#define F4_TOTAL (An * Kn / 4)        /* 2,000,000 float4 per image */
#define TPB 256
#define ITERS 8
#define F4_PER_BLK (TPB * ITERS)      /* 2048 float4 per block */
#define GX ((F4_TOTAL + F4_PER_BLK - 1) / F4_PER_BLK)   /* 977 */
#define MAXA 110

// ---------------- device scratch (per-block partials, written unconditionally
// every run -> no init kernel, no atomics, graph-replay safe) ----------------
__device__ float g_part_cls [Bn * GX];
__device__ float g_part_reg [Bn * GX];
__device__ float g_part_npos[Bn * GX];

// ---------------- fast MUFU intrinsics ------------------------------------
__device__ __forceinline__ float fast_ex2(float x) { float r; asm("ex2.approx.f32 %0, %1;" : "=f"(r) : "f"(x)); return r; }
__device__ __forceinline__ float fast_lg2(float x) { float r; asm("lg2.approx.f32 %0, %1;" : "=f"(r) : "f"(x)); return r; }
__device__ __forceinline__ float fast_rcp(float x) { float r; asm("rcp.approx.f32 %0, %1;" : "=f"(r) : "f"(x)); return r; }

// Branch-1 focal loss (targets != 0): f1(x) = 0.25*(1-sigmoid(x))^2*softplus(-x)
//   = 0.25 * e^2 * ln(1+e)/(1+e)^2   with e = exp(-x) in (0.368, 1]
// Degree-7 Taylor of 0.25*ln(1+e)/(1+e)^2 around e0 = 0.6839385.
// Validated: e=1 -> 0.25*ln2/4 (err 4e-6 rel 2.4e-5), e=0.368 (rel 5e-5), e=0.85 (rel 3e-6).
__device__ __forceinline__ float focal_neg(float x) {
    float e = fast_ex2(-1.44269504f * x);      // exp(-x), 1 MUFU
    float s = e - 0.6839385f;
    float p =             0.02198625f;
    p = fmaf(p, s, -0.02900980f);
    p = fmaf(p, s,  0.03629070f);
    p = fmaf(p, s, -0.04178675f);
    p = fmaf(p, s,  0.04151668f);
    p = fmaf(p, s, -0.02911970f);
    p = fmaf(p, s, -0.00221338f);
    p = fmaf(p, s,  0.04594508f);
    return (e * e) * p;
}

// Branch-2 (rare: positive anchor, non-assigned class): 0.75*p^2*(x+softplus(-x))
__device__ __forceinline__ float focal_pos_other(float c) {
    float x = fminf(fmaxf(c, 1e-4f), 0.9999f);
    float e = fast_ex2(-1.44269504f * x);
    float q = 1.0f + e;
    float u = fast_rcp(q);
    float sp = 0.69314718f * fast_lg2(q);
    return 0.75f * (u * u) * (x + sp);
}

// ---------------- fused kernel: IoU assignment + regression + focal -------
__global__ void __launch_bounds__(TPB) fused_kernel(
    const float* __restrict__ cls,
    const float* __restrict__ regs,
    const float* __restrict__ anc,
    const float* __restrict__ ann)
{
    __shared__ float bx1[Mn], by1[Mn], bx2[Mn], by2[Mn], barea[Mn], blab[Mn];
    __shared__ int   bval[Mn];
    __shared__ signed char sc[MAXA];
    __shared__ float s_reg, s_npos;
    __shared__ float wsum[TPB / 32];

    const int b = blockIdx.y;
    const int t = threadIdx.x;
    const int F0   = blockIdx.x * F4_PER_BLK;
    const int Fend = min(F0 + F4_PER_BLK, F4_TOTAL);
    const int A0 = F0 / 20;
    const int A1 = (Fend - 1) / 20;
    const int nA = A1 - A0 + 1;           // <= 104

    if (t == 0) { s_reg = 0.f; s_npos = 0.f; }
    if (t < Mn) {
        const float* a5 = ann + ((size_t)b * Mn + t) * 5;
        float x1 = a5[0], y1 = a5[1], x2 = a5[2], y2 = a5[3], lb = a5[4];
        bx1[t] = x1; by1[t] = y1; bx2[t] = x2; by2[t] = y2;
        barea[t] = (x2 - x1) * (y2 - y1);
        blab[t] = lb;
        bval[t] = (lb != -1.0f);
    }
    __syncthreads();

    // ---- phase 1: assignment for the <=104 anchors this block touches ----
    if (t < nA) {
        int a = A0 + t;
        float ax1 = anc[a * 4 + 0], ay1 = anc[a * 4 + 1];
        float ax2 = anc[a * 4 + 2], ay2 = anc[a * 4 + 3];
        float areaA = (ax2 - ax1) * (ay2 - ay1);

        float best = -1e30f; int bi = 0;
        #pragma unroll
        for (int m = 0; m < Mn; m++) {
            float iou;
            if (bval[m]) {
                float iw = fminf(ax2, bx2[m]) - fmaxf(ax1, bx1[m]); iw = fmaxf(iw, 0.f);
                float ih = fminf(ay2, by2[m]) - fmaxf(ay1, by1[m]); ih = fmaxf(ih, 0.f);
                float inter = iw * ih;
                float ua = fmaxf(areaA + barea[m] - inter, 1e-8f);
                iou = inter / ua;          // IEEE div: thresholds must match ref
            } else {
                iou = -1.0f;
            }
            if (iou > best) { best = iou; bi = m; }   // first-max = jnp.argmax
        }
        bool pos = (best >= 0.5f);
        sc[t] = pos ? (signed char)(int)blab[bi] : (signed char)(-1);

        // ownership: the block containing the anchor's first float4 owns it
        if (pos && a * 20 >= F0 && a * 20 < Fend) {
            atomicAdd(&s_npos, 1.0f);
            float aw = ax2 - ax1, ah = ay2 - ay1;
            float acx = ax1 + 0.5f * aw, acy = ay1 + 0.5f * ah;
            float gw = bx2[bi] - bx1[bi], gh = by2[bi] - by1[bi];
            float gcx = bx1[bi] + 0.5f * gw, gcy = by1[bi] + 0.5f * gh;
            gw = fmaxf(gw, 1.0f); gh = fmaxf(gh, 1.0f);
            float tt[4];
            tt[0] = ((gcx - acx) / aw) / 0.1f;
            tt[1] = ((gcy - acy) / ah) / 0.1f;
            tt[2] = logf(gw / aw) / 0.2f;
            tt[3] = logf(gh / ah) / 0.2f;
            const float* r = regs + ((size_t)b * An + a) * 4;
            float srl = 0.f;
            #pragma unroll
            for (int j = 0; j < 4; j++) {
                float d = fabsf(tt[j] - r[j]);
                float sl = (d <= (float)(1.0 / 9.0)) ? 4.5f * d * d : d - (float)(0.5 / 9.0);
                srl += sl;
            }
            atomicAdd(&s_reg, srl);
        }
    }
    __syncthreads();

    // ---- phase 2: focal classification loss over this block's 2048 float4 ----
    const float4* __restrict__ src = (const float4*)cls + (size_t)b * F4_TOTAL;
    float acc = 0.f;

    if (F0 + F4_PER_BLK <= F4_TOTAL) {
        // fast path: no bounds checks -> ptxas can front-batch the 8 LDG.128
        #pragma unroll
        for (int it = 0; it < ITERS; it++) {
            int idx = F0 + it * TPB + t;
            int q = idx / 20;                 // const-div -> umulhi+shift
            int code = sc[q - A0];
            float4 v = src[idx];
            if (code < 0) {
                acc += focal_neg(v.x);
                acc += focal_neg(v.y);
                acc += focal_neg(v.z);
                acc += focal_neg(v.w);
            } else {
                int k0 = (idx - q * 20) * 4;
                acc += (k0 + 0 == code) ? focal_neg(fminf(fmaxf(v.x,1e-4f),0.9999f)) : focal_pos_other(v.x);
                acc += (k0 + 1 == code) ? focal_neg(fminf(fmaxf(v.y,1e-4f),0.9999f)) : focal_pos_other(v.y);
                acc += (k0 + 2 == code) ? focal_neg(fminf(fmaxf(v.z,1e-4f),0.9999f)) : focal_pos_other(v.z);
                acc += (k0 + 3 == code) ? focal_neg(fminf(fmaxf(v.w,1e-4f),0.9999f)) : focal_pos_other(v.w);
            }
        }
    } else {
        #pragma unroll
        for (int it = 0; it < ITERS; it++) {
            int idx = F0 + it * TPB + t;
            if (idx < Fend) {
                int q = idx / 20;
                int code = sc[q - A0];
                float4 v = src[idx];
                if (code < 0) {
                    acc += focal_neg(v.x); acc += focal_neg(v.y);
                    acc += focal_neg(v.z); acc += focal_neg(v.w);
                } else {
                    int k0 = (idx - q * 20) * 4;
                    acc += (k0 + 0 == code) ? focal_neg(fminf(fmaxf(v.x,1e-4f),0.9999f)) : focal_pos_other(v.x);
                    acc += (k0 + 1 == code) ? focal_neg(fminf(fmaxf(v.y,1e-4f),0.9999f)) : focal_pos_other(v.y);
                    acc += (k0 + 2 == code) ? focal_neg(fminf(fmaxf(v.z,1e-4f),0.9999f)) : focal_pos_other(v.z);
                    acc += (k0 + 3 == code) ? focal_neg(fminf(fmaxf(v.w,1e-4f),0.9999f)) : focal_pos_other(v.w);
                }
            }
        }
    }

    // ---- block reduction + partial write ----
    #pragma unroll
    for (int o = 16; o > 0; o >>= 1) acc += __shfl_down_sync(0xffffffffu, acc, o);
    if ((t & 31) == 0) wsum[t >> 5] = acc;
    __syncthreads();
    if (t == 0) {
        float v = 0.f;
        #pragma unroll
        for (int w = 0; w < TPB / 32; w++) v += wsum[w];
        int bid = b * GX + blockIdx.x;
        g_part_cls [bid] = v;
        g_part_reg [bid] = s_reg;
        g_part_npos[bid] = s_npos;
    }
}

// ---------------- final reduce: 8*977 partials -> 2 outputs ----------------
__global__ void __launch_bounds__(1024) final_kernel(
    const float* __restrict__ ann, float* __restrict__ out, int out_size)
{
    __shared__ float rc[32], rr[32], rn[32];   // 8 images x 4 warps
    const int t = threadIdx.x;
    const int img = t >> 7;         // 128 threads per image
    const int lt = t & 127;

    float c = 0.f, r = 0.f, n = 0.f;
    for (int j = lt; j < GX; j += 128) {
        int bid = img * GX + j;
        c += g_part_cls[bid];
        r += g_part_reg[bid];
        n += g_part_npos[bid];
    }
    #pragma unroll
    for (int o = 16; o > 0; o >>= 1) {
        c += __shfl_down_sync(0xffffffffu, c, o);
        r += __shfl_down_sync(0xffffffffu, r, o);
        n += __shfl_down_sync(0xffffffffu, n, o);
    }
    if ((t & 31) == 0) { rc[t >> 5] = c; rr[t >> 5] = r; rn[t >> 5] = n; }
    __syncthreads();

    if (t < Bn) {
        float C = 0.f, R = 0.f, N = 0.f;
        #pragma unroll
        for (int w = 0; w < 4; w++) { C += rc[t * 4 + w]; R += rr[t * 4 + w]; N += rn[t * 4 + w]; }
        bool has = false;
        #pragma unroll
        for (int m = 0; m < Mn; m++)
            has = has || (ann[((size_t)t * Mn + m) * 5 + 4] != -1.0f);
        float clsv = C / fmaxf(N, 0.01f);
        float regv = (N > 0.f) ? (R / fmaxf(N * 4.0f, 1.0f)) : 0.f;
        if (!has) { clsv = 0.f; regv = 0.f; }
        #pragma unroll
        for (int o = 4; o > 0; o >>= 1) {
            clsv += __shfl_down_sync(0x000000ffu, clsv, o);
            regv += __shfl_down_sync(0x000000ffu, regv, o);
        }
        if (t == 0) {
            out[0] = clsv * (1.0f / (float)Bn);
            if (out_size > 1) out[1] = regv * (1.0f / (float)Bn);
        }
    }
}

// ---------------- launch ---------------------------------------------------
extern "C" void kernel_launch(void* const* d_in, const int* in_sizes, int n_in,
                              void* d_out, int out_size) {
    const float *cls = nullptr, *reg = nullptr, *anc = nullptr, *ann = nullptr;
    for (int i = 0; i < n_in; i++) {
        long long sz = in_sizes[i];
        if      (sz == (long long)Bn * An * Kn) cls = (const float*)d_in[i];
        else if (sz == (long long)Bn * An * 4)  reg = (const float*)d_in[i];
        else if (sz == (long long)An * 4)       anc = (const float*)d_in[i];
        else if (sz == (long long)Bn * Mn * 5)  ann = (const float*)d_in[i];
    }

    dim3 g(GX, Bn);
    fused_kernel<<<g, TPB>>>(cls, reg, anc, ann);
    final_kernel<<<1, 1024>>>(ann, (float*)d_out, out_size);
}

// round 3
// speedup vs baseline: 1.2726x; 1.2726x over previous
#include <cuda_runtime.h>
#include <math.h>

#define Bn 8
#define An 100000
#define Kn 80
#define Mn 32
#define F4_TOTAL (An * Kn / 4)          /* 2,000,000 float4 per image */
#define TPB 256
#define ITERS 4
#define F4_PER_BLK (TPB * ITERS)        /* 1024 */
#define GX ((F4_TOTAL + F4_PER_BLK - 1) / F4_PER_BLK)   /* 1954 */
#define AGX ((An + TPB - 1) / TPB)      /* 391 */
#define NBLOCKS (Bn * GX)               /* 15632 */

typedef unsigned long long u64;

// ---------------- device scratch (written every run, no init needed) -------
__device__ signed char g_codes[(size_t)Bn * An];
__device__ float g_pcls[Bn * GX];
__device__ float g_preg[Bn * AGX];
__device__ float g_pnp [Bn * AGX];
__device__ unsigned int g_done;         // zero-init at load; reset in-kernel

// ---------------- fast intrinsics ------------------------------------------
__device__ __forceinline__ float fast_ex2(float x) { float r; asm("ex2.approx.f32 %0, %1;" : "=f"(r) : "f"(x)); return r; }
__device__ __forceinline__ float fast_lg2(float x) { float r; asm("lg2.approx.f32 %0, %1;" : "=f"(r) : "f"(x)); return r; }
__device__ __forceinline__ float fast_rcp(float x) { float r; asm("rcp.approx.f32 %0, %1;" : "=f"(r) : "f"(x)); return r; }

// ---------------- packed f32x2 helpers (sm_103a) ---------------------------
__device__ __forceinline__ u64 pkf(float lo, float hi) {
    u64 r;
    asm("mov.b64 %0, {%1, %2};" : "=l"(r) : "r"(__float_as_uint(lo)), "r"(__float_as_uint(hi)));
    return r;
}
__device__ __forceinline__ void upkf(u64 v, float& lo, float& hi) {
    unsigned a, b;
    asm("mov.b64 {%0, %1}, %2;" : "=r"(a), "=r"(b) : "l"(v));
    lo = __uint_as_float(a); hi = __uint_as_float(b);
}
__device__ __forceinline__ u64 fma2(u64 a, u64 b, u64 c) {
    u64 d; asm("fma.rn.f32x2 %0, %1, %2, %3;" : "=l"(d) : "l"(a), "l"(b), "l"(c)); return d;
}
__device__ __forceinline__ u64 add2(u64 a, u64 b) {
    u64 d; asm("add.rn.f32x2 %0, %1, %2;" : "=l"(d) : "l"(a), "l"(b)); return d;
}
__device__ __forceinline__ u64 mul2(u64 a, u64 b) {
    u64 d; asm("mul.rn.f32x2 %0, %1, %2;" : "=l"(d) : "l"(a), "l"(b)); return d;
}
__device__ __forceinline__ u64 pk2c(float c) {
    unsigned u = __float_as_uint(c);
    return ((u64)u << 32) | (u64)u;
}

// ---- focal branch-1 (targets != 0), VALIDATED in round 2 (rel_err 3.7e-6) --
// f1(x) = 0.25*e^2*ln(1+e)/(1+e)^2, e = exp(-x); degree-7 Taylor around e0.
#define CF7  0.02198625f
#define CF6 -0.02900980f
#define CF5  0.03629070f
#define CF4 -0.04178675f
#define CF3  0.04151668f
#define CF2 -0.02911970f
#define CF1 -0.00221338f
#define CF0  0.04594508f
#define E0C  0.6839385f

struct PolyC { u64 e0n, c7, c6, c5, c4, c3, c2, c1, c0; };

__device__ __forceinline__ u64 focal_pair_acc(u64 acc, float xa, float xb, const PolyC& K) {
    float ea = fast_ex2(-1.44269504f * xa);
    float eb = fast_ex2(-1.44269504f * xb);
    u64 e2 = pkf(ea, eb);
    u64 s  = add2(e2, K.e0n);               // e - e0
    u64 p  = fma2(K.c7, s, K.c6);
    p = fma2(p, s, K.c5);
    p = fma2(p, s, K.c4);
    p = fma2(p, s, K.c3);
    p = fma2(p, s, K.c2);
    p = fma2(p, s, K.c1);
    p = fma2(p, s, K.c0);
    u64 esq = mul2(e2, e2);
    return fma2(esq, p, acc);               // acc += e^2 * p
}

__device__ __forceinline__ float focal_neg_scalar(float c) {
    float x = fminf(fmaxf(c, 1e-4f), 0.9999f);
    float e = fast_ex2(-1.44269504f * x);
    float s = e - E0C;
    float p = CF7;
    p = fmaf(p, s, CF6); p = fmaf(p, s, CF5); p = fmaf(p, s, CF4);
    p = fmaf(p, s, CF3); p = fmaf(p, s, CF2); p = fmaf(p, s, CF1);
    p = fmaf(p, s, CF0);
    return (e * e) * p;
}

__device__ __forceinline__ float focal_pos_other(float c) {
    float x = fminf(fmaxf(c, 1e-4f), 0.9999f);
    float e = fast_ex2(-1.44269504f * x);
    float q = 1.0f + e;
    float u = fast_rcp(q);
    float sp = 0.69314718f * fast_lg2(q);
    return 0.75f * (u * u) * (x + sp);
}

// ---------------- kernel A: IoU assignment (each anchor once, as R1) -------
__global__ void __launch_bounds__(TPB) assign_kernel(
    const float* __restrict__ anc, const float* __restrict__ ann,
    const float* __restrict__ regs)
{
    __shared__ float bx1[Mn], by1[Mn], bx2[Mn], by2[Mn], barea[Mn], blab[Mn];
    __shared__ int   bval[Mn];
    __shared__ float wnp[TPB / 32], wrg[TPB / 32];

    const int b = blockIdx.y;
    const int t = threadIdx.x;
    if (t < Mn) {
        const float* a5 = ann + ((size_t)b * Mn + t) * 5;
        float x1 = a5[0], y1 = a5[1], x2 = a5[2], y2 = a5[3], lb = a5[4];
        bx1[t] = x1; by1[t] = y1; bx2[t] = x2; by2[t] = y2;
        barea[t] = (x2 - x1) * (y2 - y1);
        blab[t] = lb;
        bval[t] = (lb != -1.0f);
    }
    __syncthreads();

    const int a = blockIdx.x * TPB + t;
    float npos = 0.f, srl = 0.f;
    if (a < An) {
        float ax1 = anc[a * 4 + 0], ay1 = anc[a * 4 + 1];
        float ax2 = anc[a * 4 + 2], ay2 = anc[a * 4 + 3];
        float areaA = (ax2 - ax1) * (ay2 - ay1);

        float best = -1e30f; int bi = 0;
        #pragma unroll
        for (int m = 0; m < Mn; m++) {
            float iou;
            if (bval[m]) {
                float iw = fminf(ax2, bx2[m]) - fmaxf(ax1, bx1[m]); iw = fmaxf(iw, 0.f);
                float ih = fminf(ay2, by2[m]) - fmaxf(ay1, by1[m]); ih = fmaxf(ih, 0.f);
                float inter = iw * ih;
                float ua = fmaxf(areaA + barea[m] - inter, 1e-8f);
                iou = inter / ua;       // IEEE div: decisions must match reference
            } else {
                iou = -1.0f;
            }
            if (iou > best) { best = iou; bi = m; }   // first-max = jnp.argmax
        }
        bool pos = (best >= 0.5f);
        g_codes[(size_t)b * An + a] = pos ? (signed char)(int)blab[bi] : (signed char)(-1);

        if (pos) {
            npos = 1.f;
            float aw = ax2 - ax1, ah = ay2 - ay1;
            float acx = ax1 + 0.5f * aw, acy = ay1 + 0.5f * ah;
            float gw = bx2[bi] - bx1[bi], gh = by2[bi] - by1[bi];
            float gcx = bx1[bi] + 0.5f * gw, gcy = by1[bi] + 0.5f * gh;
            gw = fmaxf(gw, 1.0f); gh = fmaxf(gh, 1.0f);
            float tt[4];
            tt[0] = ((gcx - acx) / aw) / 0.1f;
            tt[1] = ((gcy - acy) / ah) / 0.1f;
            tt[2] = logf(gw / aw) / 0.2f;
            tt[3] = logf(gh / ah) / 0.2f;
            const float* r = regs + ((size_t)b * An + a) * 4;
            #pragma unroll
            for (int j = 0; j < 4; j++) {
                float d = fabsf(tt[j] - r[j]);
                srl += (d <= (float)(1.0 / 9.0)) ? 4.5f * d * d : d - (float)(0.5 / 9.0);
            }
        }
    }

    #pragma unroll
    for (int o = 16; o > 0; o >>= 1) {
        npos += __shfl_down_sync(0xffffffffu, npos, o);
        srl  += __shfl_down_sync(0xffffffffu, srl,  o);
    }
    if ((t & 31) == 0) { wnp[t >> 5] = npos; wrg[t >> 5] = srl; }
    __syncthreads();
    if (t == 0) {
        float n = 0.f, s = 0.f;
        #pragma unroll
        for (int w = 0; w < TPB / 32; w++) { n += wnp[w]; s += wrg[w]; }
        g_pnp [b * AGX + blockIdx.x] = n;
        g_preg[b * AGX + blockIdx.x] = s;
    }
}

// ---------------- kernel B: focal loss + last-block final reduce -----------
__global__ void __launch_bounds__(TPB) focal_kernel(
    const float* __restrict__ cls, const float* __restrict__ ann,
    float* __restrict__ out, int out_size)
{
    __shared__ float wsum[TPB / 32];
    __shared__ int s_elect;
    __shared__ float s_c[Bn], s_r[Bn];

    const int b = blockIdx.y;
    const int t = threadIdx.x;
    const int F0 = blockIdx.x * F4_PER_BLK;
    const float4* __restrict__ src = (const float4*)cls + (size_t)b * F4_TOTAL;
    const signed char* __restrict__ codes = g_codes + (size_t)b * An;

    PolyC K;
    K.e0n = pk2c(-E0C);
    K.c7 = pk2c(CF7); K.c6 = pk2c(CF6); K.c5 = pk2c(CF5); K.c4 = pk2c(CF4);
    K.c3 = pk2c(CF3); K.c2 = pk2c(CF2); K.c1 = pk2c(CF1); K.c0 = pk2c(CF0);

    u64 acc2 = 0ull;          // packed (0.f, 0.f)
    float accs = 0.f;         // rare scalar path

    if (F0 + F4_PER_BLK <= F4_TOTAL) {
        #pragma unroll
        for (int it = 0; it < ITERS; it++) {
            int idx = F0 + it * TPB + t;
            float4 v = __ldcs(&src[idx]);       // streaming: no reuse
            int q = idx / 20;                   // const-div -> umulhi
            int code = codes[q];
            if (code < 0) {
                acc2 = focal_pair_acc(acc2, v.x, v.y, K);
                acc2 = focal_pair_acc(acc2, v.z, v.w, K);
            } else {
                int k0 = (idx - q * 20) * 4;
                accs += (k0 + 0 == code) ? focal_neg_scalar(v.x) : focal_pos_other(v.x);
                accs += (k0 + 1 == code) ? focal_neg_scalar(v.y) : focal_pos_other(v.y);
                accs += (k0 + 2 == code) ? focal_neg_scalar(v.z) : focal_pos_other(v.z);
                accs += (k0 + 3 == code) ? focal_neg_scalar(v.w) : focal_pos_other(v.w);
            }
        }
    } else {
        #pragma unroll
        for (int it = 0; it < ITERS; it++) {
            int idx = F0 + it * TPB + t;
            if (idx < F4_TOTAL) {
                float4 v = __ldcs(&src[idx]);
                int q = idx / 20;
                int code = codes[q];
                if (code < 0) {
                    acc2 = focal_pair_acc(acc2, v.x, v.y, K);
                    acc2 = focal_pair_acc(acc2, v.z, v.w, K);
                } else {
                    int k0 = (idx - q * 20) * 4;
                    accs += (k0 + 0 == code) ? focal_neg_scalar(v.x) : focal_pos_other(v.x);
                    accs += (k0 + 1 == code) ? focal_neg_scalar(v.y) : focal_pos_other(v.y);
                    accs += (k0 + 2 == code) ? focal_neg_scalar(v.z) : focal_pos_other(v.z);
                    accs += (k0 + 3 == code) ? focal_neg_scalar(v.w) : focal_pos_other(v.w);
                }
            }
        }
    }

    float lo, hi; upkf(acc2, lo, hi);
    float acc = lo + hi + accs;

    #pragma unroll
    for (int o = 16; o > 0; o >>= 1) acc += __shfl_down_sync(0xffffffffu, acc, o);
    if ((t & 31) == 0) wsum[t >> 5] = acc;
    __syncthreads();
    if (t == 0) {
        float v = 0.f;
        #pragma unroll
        for (int w = 0; w < TPB / 32; w++) v += wsum[w];
        g_pcls[b * GX + blockIdx.x] = v;
        __threadfence();
        unsigned d = atomicAdd(&g_done, 1u);
        s_elect = (d == (unsigned)(NBLOCKS - 1));
    }
    __syncthreads();

    // ---- last block performs the final reduce (partials are L2-hot) ----
    if (s_elect) {
        const int w = t >> 5;       // warp w handles image w (8 warps)
        const int lane = t & 31;
        float C = 0.f, R = 0.f, N = 0.f;
        for (int j = lane; j < GX; j += 32) C += g_pcls[w * GX + j];
        for (int j = lane; j < AGX; j += 32) { R += g_preg[w * AGX + j]; N += g_pnp[w * AGX + j]; }
        #pragma unroll
        for (int o = 16; o > 0; o >>= 1) {
            C += __shfl_down_sync(0xffffffffu, C, o);
            R += __shfl_down_sync(0xffffffffu, R, o);
            N += __shfl_down_sync(0xffffffffu, N, o);
        }
        float lab = ann[((size_t)w * Mn + lane) * 5 + 4];
        unsigned hasmask = __ballot_sync(0xffffffffu, lab != -1.0f);
        if (lane == 0) {
            float clsv = C / fmaxf(N, 0.01f);
            float regv = (N > 0.f) ? (R / fmaxf(N * 4.0f, 1.0f)) : 0.f;
            if (hasmask == 0u) { clsv = 0.f; regv = 0.f; }
            s_c[w] = clsv; s_r[w] = regv;
        }
        __syncthreads();
        if (t == 0) {
            float sc = 0.f, sr = 0.f;
            #pragma unroll
            for (int i = 0; i < Bn; i++) { sc += s_c[i]; sr += s_r[i]; }
            out[0] = sc * (1.0f / (float)Bn);
            if (out_size > 1) out[1] = sr * (1.0f / (float)Bn);
            g_done = 0;      // reset for next graph replay
        }
    }
}

// ---------------- launch ---------------------------------------------------
extern "C" void kernel_launch(void* const* d_in, const int* in_sizes, int n_in,
                              void* d_out, int out_size) {
    const float *cls = nullptr, *reg = nullptr, *anc = nullptr, *ann = nullptr;
    for (int i = 0; i < n_in; i++) {
        long long sz = in_sizes[i];
        if      (sz == (long long)Bn * An * Kn) cls = (const float*)d_in[i];
        else if (sz == (long long)Bn * An * 4)  reg = (const float*)d_in[i];
        else if (sz == (long long)An * 4)       anc = (const float*)d_in[i];
        else if (sz == (long long)Bn * Mn * 5)  ann = (const float*)d_in[i];
    }

    dim3 ga(AGX, Bn);
    assign_kernel<<<ga, TPB>>>(anc, ann, reg);

    dim3 gf(GX, Bn);
    focal_kernel<<<gf, TPB>>>(cls, ann, (float*)d_out, out_size);
}